// round 16
// baseline (speedup 1.0000x reference)
#include <cuda_runtime.h>
#include <cstdint>

#define NUM_USERS 100000
#define NUM_ITEMS 50000
#define N_NODES   150000
#define EMB       64
#define BATCH     16384
#define NNZ_MAX   2400000
#define CAP       128           // bucket capacity per row (Poisson(16); P(ovf)~0)

typedef unsigned long long u64;

// ---------------- f32x2 packed-math helpers (sm_103a) -----------------------
__device__ __forceinline__ u64 pack2(float lo, float hi) {
    u64 r;
    asm("mov.b64 %0, {%1, %2};" : "=l"(r) : "f"(lo), "f"(hi));
    return r;
}
__device__ __forceinline__ void unpack2(u64 v, float& lo, float& hi) {
    asm("mov.b64 {%0, %1}, %2;" : "=f"(lo), "=f"(hi) : "l"(v));
}
__device__ __forceinline__ u64 fma2(u64 a, u64 b, u64 c) {
    u64 d;
    asm("fma.rn.f32x2 %0, %1, %2, %3;" : "=l"(d) : "l"(a), "l"(b), "l"(c));
    return d;
}

// ---------------- scratch (static device allocations; no cudaMalloc) --------
__device__ float g_y    [N_NODES * EMB];   // y = x @ W   (current layer)
__device__ float g_feat1[N_NODES * EMB];   // layer-1 output
__device__ float g_feat2[N_NODES * EMB];   // layer-2 output (only gathered rows valid)
__device__ int   g_cnt[N_NODES];           // bucket fill counts (memset 0 each call)
__device__ int2  g_bedges[(size_t)N_NODES * CAP];  // per-row edge buckets

// Split-pointer node row lookup (layer-1 reads raw embeddings; for contiguous
// buffers pass u=base, i=base+U*64).
__device__ __forceinline__ const float* node_row(const float* __restrict__ u,
                                                 const float* __restrict__ i,
                                                 int node) {
    return (node < NUM_USERS) ? (u + (size_t)node * EMB)
                              : (i + (size_t)(node - NUM_USERS) * EMB);
}

// ---------------- bucket scatter: one pass builds the whole structure -------
__global__ void scatter_bucket_kernel(const int*   __restrict__ rows,
                                      const int*   __restrict__ cols,
                                      const float* __restrict__ vals, int nnz) {
    int e = blockIdx.x * 256 + threadIdx.x;
    if (e >= nnz) return;
    int r = rows[e];
    int pos = atomicAdd(&g_cnt[r], 1);
    if (pos < CAP)
        g_bedges[(size_t)r * CAP + pos] = make_int2(cols[e], __float_as_int(vals[e]));
}

// ---------------- dense GEMM: y = x @ W[64,64]  (no bias, no relu) ----------
// Block = 64 rows; x staged transposed in smem as row-pairs; inner loop is
// LDS.64 broadcast + packed fma.rn.f32x2. Warp = 8 rows (4 pairs).
__global__ __launch_bounds__(256)
void gemm_kernel(const float* __restrict__ xu,
                 const float* __restrict__ xi,
                 const float* __restrict__ W,
                 float* __restrict__ y, int nrows) {
    __shared__ float2 sW[64 * 32];     // sW[k*32+j] = (W[k][j], W[k][j+32])
    __shared__ float2 sXT[64 * 33];    // sXT[k*33+rp] = (x[2rp][k], x[2rp+1][k])
    int tid = threadIdx.x;
    #pragma unroll
    for (int i = tid; i < 2048; i += 256) {
        int k = i >> 5, j = i & 31;
        sW[i] = make_float2(W[k * 64 + j], W[k * 64 + j + 32]);
    }
    int r_base = blockIdx.x * 64;
    #pragma unroll
    for (int i = tid; i < 4096; i += 256) {
        int row = i >> 6, k = i & 63;
        int grow = r_base + row;
        float v = (grow < nrows) ? node_row(xu, xi, grow)[k] : 0.f;
        ((float*)&sXT[k * 33 + (row >> 1)])[row & 1] = v;
    }
    __syncthreads();

    int lane = tid & 31, warp = tid >> 5;
    int rp_base = warp * 4;

    u64 po0[4], po1[4];
    #pragma unroll
    for (int rp = 0; rp < 4; rp++) { po0[rp] = 0ull; po1[rp] = 0ull; }

    #pragma unroll 4
    for (int k = 0; k < 64; k++) {
        float2 w = sW[k * 32 + lane];
        u64 wxx = pack2(w.x, w.x);
        u64 wyy = pack2(w.y, w.y);
        #pragma unroll
        for (int rp = 0; rp < 4; rp++) {
            u64 xp = *(const u64*)&sXT[k * 33 + rp_base + rp];
            po0[rp] = fma2(xp, wxx, po0[rp]);
            po1[rp] = fma2(xp, wyy, po1[rp]);
        }
    }

    #pragma unroll
    for (int rp = 0; rp < 4; rp++) {
        int row0 = r_base + warp * 8 + rp * 2;
        float lo0, hi0, lo1, hi1;
        unpack2(po0[rp], lo0, hi0);
        unpack2(po1[rp], lo1, hi1);
        if (row0 < nrows) {
            y[(size_t)row0 * 64 + lane]      = lo0;
            y[(size_t)row0 * 64 + lane + 32] = lo1;
        }
        if (row0 + 1 < nrows) {
            y[(size_t)(row0 + 1) * 64 + lane]      = hi0;
            y[(size_t)(row0 + 1) * 64 + lane + 32] = hi1;
        }
    }
}

// ---------------- SpMM (all rows): out = relu(L @ y + y + b) ----------------
// Bucketed: warp = 8 rows; per row, edges come from the row's contiguous
// bucket (warp-uniform broadcast loads); 8-edge batches keep gathers in flight.
__global__ __launch_bounds__(256)
void spmm_relu_kernel(const float* __restrict__ y,
                      const float* __restrict__ b,
                      float* __restrict__ out, int nrows) {
    __shared__ float sb[64];
    int tid = threadIdx.x;
    if (tid < 64) sb[tid] = b[tid];
    __syncthreads();

    int lane = tid & 31, warp = tid >> 5;
    int r0 = blockIdx.x * 64 + warp * 8;

    #pragma unroll
    for (int rr = 0; rr < 8; rr++) {
        int row = r0 + rr;
        if (row >= nrows) break;
        const float* yr = y + (size_t)row * 64;
        float a0 = yr[lane]      + sb[lane];        // self loop + bias
        float a1 = yr[lane + 32] + sb[lane + 32];
        int cnt = min(g_cnt[row], CAP);
        const int2* ep = g_bedges + (size_t)row * CAP;
        int i = 0;
        for (; i + 8 <= cnt; i += 8) {
            int2 c[8];
            #pragma unroll
            for (int q = 0; q < 8; q++) c[q] = ep[i + q];
            float xs0[8], xs1[8];
            #pragma unroll
            for (int q = 0; q < 8; q++) {
                const float* yp = y + (size_t)c[q].x * 64;
                xs0[q] = yp[lane];  xs1[q] = yp[lane + 32];
            }
            #pragma unroll
            for (int q = 0; q < 8; q++) {
                float v = __int_as_float(c[q].y);
                a0 += v * xs0[q];  a1 += v * xs1[q];
            }
        }
        for (; i < cnt; i++) {
            int2 cc = ep[i];
            float v = __int_as_float(cc.y);
            const float* yp = y + (size_t)cc.x * 64;
            a0 += v * yp[lane];
            a1 += v * yp[lane + 32];
        }
        float* op = out + (size_t)row * 64;
        op[lane]      = fmaxf(a0, 0.f);
        op[lane + 32] = fmaxf(a1, 0.f);
    }
}

// ---------------- SpMM (gathered rows only): layer-2 shortcut ---------------
// feat2 only read at userIdx / itemIdx+U -> compute exactly those 32768 rows
// (duplicates recompute identical values; benign).
__global__ __launch_bounds__(256)
void spmm_relu_idx_kernel(const int*   __restrict__ userIdx,
                          const int*   __restrict__ itemIdx,
                          const float* __restrict__ y,
                          const float* __restrict__ b,
                          float* __restrict__ out) {
    __shared__ float sb[64];
    int tid = threadIdx.x;
    if (tid < 64) sb[tid] = b[tid];
    __syncthreads();

    int lane = tid & 31, warp = tid >> 5;
    int base = blockIdx.x * 64 + warp * 8;     // entry index base (0..32767)

    #pragma unroll
    for (int rr = 0; rr < 8; rr++) {
        int ent = base + rr;
        int row = (ent < BATCH) ? __ldg(userIdx + ent)
                                : (__ldg(itemIdx + ent - BATCH) + NUM_USERS);
        const float* yr = y + (size_t)row * 64;
        float a0 = yr[lane]      + sb[lane];
        float a1 = yr[lane + 32] + sb[lane + 32];
        int cnt = min(g_cnt[row], CAP);
        const int2* ep = g_bedges + (size_t)row * CAP;
        int i = 0;
        for (; i + 8 <= cnt; i += 8) {
            int2 c[8];
            #pragma unroll
            for (int q = 0; q < 8; q++) c[q] = ep[i + q];
            float xs0[8], xs1[8];
            #pragma unroll
            for (int q = 0; q < 8; q++) {
                const float* yp = y + (size_t)c[q].x * 64;
                xs0[q] = yp[lane];  xs1[q] = yp[lane + 32];
            }
            #pragma unroll
            for (int q = 0; q < 8; q++) {
                float v = __int_as_float(c[q].y);
                a0 += v * xs0[q];  a1 += v * xs1[q];
            }
        }
        for (; i < cnt; i++) {
            int2 cc = ep[i];
            float v = __int_as_float(cc.y);
            const float* yp = y + (size_t)cc.x * 64;
            a0 += v * yp[lane];
            a1 += v * yp[lane + 32];
        }
        float* op = out + (size_t)row * 64;
        op[lane]      = fmaxf(a0, 0.f);
        op[lane + 32] = fmaxf(a1, 0.f);
    }
}

// ---------------- fused gather + 3-layer MLP --------------------------------
__global__ __launch_bounds__(256)
void mlp_fused_kernel(const int*   __restrict__ userIdx,
                      const int*   __restrict__ itemIdx,
                      const float* __restrict__ uEmb,
                      const float* __restrict__ iEmb,
                      const float* __restrict__ W1, const float* __restrict__ b1,
                      const float* __restrict__ W2, const float* __restrict__ b2,
                      const float* __restrict__ W3, const float* __restrict__ b3,
                      float* __restrict__ out) {
    __shared__ float2 sW[64 * 32];    // current W1 segment, paired cols
    __shared__ float  sW2[64 * 32];
    __shared__ float  sb2[32], sW3[32];
    __shared__ float  sb3;

    int tid = threadIdx.x, lane = tid & 31, warp = tid >> 5;
    #pragma unroll
    for (int i = tid; i < 2048; i += 256) sW2[i] = W2[i];
    if (tid < 32) { sb2[tid] = b2[tid]; sW3[tid] = W3[tid]; }
    if (tid == 0) sb3 = b3[0];

    int base = blockIdx.x * 64 + warp * 8;
    int unode[8], inode[8];
    #pragma unroll
    for (int r = 0; r < 8; r++) {
        unode[r] = __ldg(userIdx + base + r);
        inode[r] = __ldg(itemIdx + base + r) + NUM_USERS;
    }

    float bb0 = __ldg(b1 + lane), bb1 = __ldg(b1 + lane + 32);
    float acc0[8], acc1[8];
    #pragma unroll
    for (int r = 0; r < 8; r++) { acc0[r] = bb0; acc1[r] = bb1; }

    #pragma unroll
    for (int kk = 0; kk < 6; kk++) {
        __syncthreads();
        #pragma unroll
        for (int i = tid; i < 2048; i += 256) {
            int k = i >> 5, j = i & 31;
            sW[i] = make_float2(W1[(kk * 64 + k) * 64 + j],
                                W1[(kk * 64 + k) * 64 + j + 32]);
        }
        __syncthreads();

        int seg = (kk < 3) ? kk : kk - 3;

        float a0[8], a1[8];
        #pragma unroll
        for (int r = 0; r < 8; r++) {
            int node = (kk < 3) ? unode[r] : inode[r];
            const float* er;
            if (seg == 0)      er = node_row(uEmb, iEmb, node);
            else if (seg == 1) er = g_feat1 + (size_t)node * 64;
            else               er = g_feat2 + (size_t)node * 64;
            a0[r] = er[lane]; a1[r] = er[lane + 32];
        }
        #pragma unroll
        for (int k = 0; k < 32; k++) {
            float2 w = sW[k * 32 + lane];
            #pragma unroll
            for (int r = 0; r < 8; r++) {
                float hk = __shfl_sync(0xffffffffu, a0[r], k);
                acc0[r] += hk * w.x;  acc1[r] += hk * w.y;
            }
        }
        #pragma unroll
        for (int k = 0; k < 32; k++) {
            float2 w = sW[(k + 32) * 32 + lane];
            #pragma unroll
            for (int r = 0; r < 8; r++) {
                float hk = __shfl_sync(0xffffffffu, a1[r], k);
                acc0[r] += hk * w.x;  acc1[r] += hk * w.y;
            }
        }
    }

    // stages 2+3, in-warp
    #pragma unroll
    for (int r = 0; r < 8; r++) {
        float m0  = fmaxf(acc0[r], 0.f);
        float m1v = fmaxf(acc1[r], 0.f);
        float acc = sb2[lane];                 // lane = output col (0..31)
        #pragma unroll
        for (int k = 0; k < 32; k++) {
            float hk = __shfl_sync(0xffffffffu, m0, k);
            acc += hk * sW2[k * 32 + lane];
        }
        #pragma unroll
        for (int k = 0; k < 32; k++) {
            float hk = __shfl_sync(0xffffffffu, m1v, k);
            acc += hk * sW2[(k + 32) * 32 + lane];
        }
        float p = acc * sW3[lane];             // no ReLU after W2 (matches ref)
        #pragma unroll
        for (int off = 16; off > 0; off >>= 1)
            p += __shfl_xor_sync(0xffffffffu, p, off);
        if (lane == 0) out[base + r] = p + sb3;
    }
}

// ---------------- launch ----------------------------------------------------
extern "C" void kernel_launch(void* const* d_in, const int* in_sizes, int n_in,
                              void* d_out, int out_size) {
    const int*   userIdx = (const int*)  d_in[0];
    const int*   itemIdx = (const int*)  d_in[1];
    const int*   lapRows = (const int*)  d_in[2];
    const int*   lapCols = (const int*)  d_in[3];
    const float* lapVals = (const float*)d_in[4];
    const float* uEmb    = (const float*)d_in[5];
    const float* iEmb    = (const float*)d_in[6];
    const float* gW0     = (const float*)d_in[7];
    const float* gb0     = (const float*)d_in[8];
    const float* gW1     = (const float*)d_in[9];
    const float* gb1     = (const float*)d_in[10];
    const float* W1      = (const float*)d_in[11];
    const float* b1      = (const float*)d_in[12];
    const float* W2      = (const float*)d_in[13];
    const float* b2      = (const float*)d_in[14];
    const float* W3      = (const float*)d_in[15];
    const float* b3      = (const float*)d_in[16];
    float* out = (float*)d_out;

    const int nnz = in_sizes[2];

    float *y, *feat1, *feat2;
    int   *cnt;
    cudaGetSymbolAddress((void**)&y,     g_y);
    cudaGetSymbolAddress((void**)&feat1, g_feat1);
    cudaGetSymbolAddress((void**)&feat2, g_feat2);
    cudaGetSymbolAddress((void**)&cnt,   g_cnt);

    const int eb = (nnz + 255) / 256;
    const int nb = (N_NODES + 63) / 64;

    // bucketed CSR: one memset + one scatter pass (no hist, no scans)
    cudaMemsetAsync(cnt, 0, N_NODES * sizeof(int));
    scatter_bucket_kernel<<<eb, 256>>>(lapRows, lapCols, lapVals, nnz); // k1

    // layer 1:  y = x@W0 ; feat1 = relu(L@y + y + b0)
    gemm_kernel<<<nb, 256>>>(uEmb, iEmb, gW0, y, N_NODES);              // k2
    spmm_relu_kernel<<<nb, 256>>>(y, gb0, feat1, N_NODES);              // k3

    // layer 2:  y = feat1@W1 ; feat2 = relu(L@y + y + b1) on gathered rows
    gemm_kernel<<<nb, 256>>>(feat1, feat1 + (size_t)NUM_USERS * EMB,
                             gW1, y, N_NODES);                          // k4
    spmm_relu_idx_kernel<<<(2 * BATCH) / 64, 256>>>(userIdx, itemIdx,
                                                    y, gb1, feat2);     // k5

    // fused gather + 3-layer MLP
    mlp_fused_kernel<<<BATCH / 64, 256>>>(userIdx, itemIdx, uEmb, iEmb,
                                          W1, b1, W2, b2, W3, b3, out); // k6
}

// round 17
// speedup vs baseline: 1.1487x; 1.1487x over previous
#include <cuda_runtime.h>
#include <cstdint>

#define NUM_USERS 100000
#define NUM_ITEMS 50000
#define N_NODES   150000
#define EMB       64
#define BATCH     16384
#define NNZ_MAX   2400000
#define NB_SCAN   ((N_NODES + 255) / 256)
#define ROWS_PER_BLOCK 64
#define EDGE_CAP  1536          // int2 staging cap per block (12 KB smem)

typedef unsigned long long u64;

// ---------------- f32x2 packed-math helpers (sm_103a) -----------------------
__device__ __forceinline__ u64 pack2(float lo, float hi) {
    u64 r;
    asm("mov.b64 %0, {%1, %2};" : "=l"(r) : "f"(lo), "f"(hi));
    return r;
}
__device__ __forceinline__ void unpack2(u64 v, float& lo, float& hi) {
    asm("mov.b64 {%0, %1}, %2;" : "=f"(lo), "=f"(hi) : "l"(v));
}
__device__ __forceinline__ u64 fma2(u64 a, u64 b, u64 c) {
    u64 d;
    asm("fma.rn.f32x2 %0, %1, %2, %3;" : "=l"(d) : "l"(a), "l"(b), "l"(c));
    return d;
}

// ---------------- scratch (static device allocations; no cudaMalloc) --------
// NOTE: g_cnt relies on BSS zero-init; scan1_kernel re-zeroes it after use so
// the zero invariant holds for every subsequent launch/graph replay.
__device__ float g_y    [N_NODES * EMB];   // y = x@W (layer1) / z = L@f1+f1 (layer2)
__device__ float g_feat1[N_NODES * EMB];   // layer-1 output
__device__ float g_feat2[N_NODES * EMB];   // layer-2 output (only gathered rows valid)
__device__ int   g_cnt[N_NODES];
__device__ int   g_rowptr[N_NODES + 1];
__device__ int   g_cursor[N_NODES];
__device__ int   g_part[NB_SCAN];
__device__ int2  g_edges[NNZ_MAX];         // sorted-by-row (col, val_bits)

// Split-pointer node row lookup (layer-1 reads raw embeddings; for contiguous
// buffers pass u=base, i=base+U*64).
__device__ __forceinline__ const float* node_row(const float* __restrict__ u,
                                                 const float* __restrict__ i,
                                                 int node) {
    return (node < NUM_USERS) ? (u + (size_t)node * EMB)
                              : (i + (size_t)(node - NUM_USERS) * EMB);
}

// ---------------- CSR build: histogram + scan + scatter ---------------------
__global__ void hist_kernel(const int* __restrict__ rows, int nnz) {
    int e = blockIdx.x * 256 + threadIdx.x;
    if (e < nnz) atomicAdd(&g_cnt[rows[e]], 1);
}

__global__ void scan1_kernel() {
    __shared__ int sm[256];
    int t = threadIdx.x;
    int i = blockIdx.x * 256 + t;
    int c = (i < N_NODES) ? g_cnt[i] : 0;
    if (i < N_NODES) g_cnt[i] = 0;                 // restore zero invariant
    sm[t] = c;
    __syncthreads();
    #pragma unroll
    for (int off = 1; off < 256; off <<= 1) {
        int v = (t >= off) ? sm[t - off] : 0;
        __syncthreads();
        sm[t] += v;
        __syncthreads();
    }
    if (i < N_NODES) g_rowptr[i] = sm[t] - c;      // block-local exclusive
    if (t == 255) g_part[blockIdx.x] = sm[255];    // block total
}

__global__ void scan23_kernel(int nnz) {
    __shared__ int red[32];
    int t = threadIdx.x;
    int partial = 0;
    for (int j = t; j < blockIdx.x; j += 256) partial += g_part[j];
    #pragma unroll
    for (int off = 16; off > 0; off >>= 1)
        partial += __shfl_xor_sync(0xffffffffu, partial, off);
    if ((t & 31) == 0) red[t >> 5] = partial;
    __syncthreads();
    int offset = red[0] + red[1] + red[2] + red[3] +
                 red[4] + red[5] + red[6] + red[7];
    int i = blockIdx.x * 256 + t;
    if (i < N_NODES) {
        int v = g_rowptr[i] + offset;
        g_rowptr[i] = v;
        g_cursor[i] = v;
    }
    if (i == 0) g_rowptr[N_NODES] = nnz;
}

__global__ void scatter_kernel(const int*   __restrict__ rows,
                               const int*   __restrict__ cols,
                               const float* __restrict__ vals, int nnz) {
    int e = blockIdx.x * 256 + threadIdx.x;
    if (e >= nnz) return;
    int r = rows[e];
    int pos = atomicAdd(&g_cursor[r], 1);
    g_edges[pos] = make_int2(cols[e], __float_as_int(vals[e]));
}

// ---------------- dense GEMM: y = x @ W[64,64]  (no bias, no relu) ----------
// Block = 64 rows; x staged transposed in smem as row-pairs; inner loop is
// LDS.64 broadcast + packed fma.rn.f32x2. Warp = 8 rows (4 pairs).
__global__ __launch_bounds__(256)
void gemm_kernel(const float* __restrict__ xu,
                 const float* __restrict__ xi,
                 const float* __restrict__ W,
                 float* __restrict__ y, int nrows) {
    __shared__ float2 sW[64 * 32];     // sW[k*32+j] = (W[k][j], W[k][j+32])
    __shared__ float2 sXT[64 * 33];    // sXT[k*33+rp] = (x[2rp][k], x[2rp+1][k])
    int tid = threadIdx.x;
    #pragma unroll
    for (int i = tid; i < 2048; i += 256) {
        int k = i >> 5, j = i & 31;
        sW[i] = make_float2(W[k * 64 + j], W[k * 64 + j + 32]);
    }
    int r_base = blockIdx.x * 64;
    #pragma unroll
    for (int i = tid; i < 4096; i += 256) {
        int row = i >> 6, k = i & 63;
        int grow = r_base + row;
        float v = (grow < nrows) ? node_row(xu, xi, grow)[k] : 0.f;
        ((float*)&sXT[k * 33 + (row >> 1)])[row & 1] = v;
    }
    __syncthreads();

    int lane = tid & 31, warp = tid >> 5;
    int rp_base = warp * 4;

    u64 po0[4], po1[4];
    #pragma unroll
    for (int rp = 0; rp < 4; rp++) { po0[rp] = 0ull; po1[rp] = 0ull; }

    #pragma unroll 4
    for (int k = 0; k < 64; k++) {
        float2 w = sW[k * 32 + lane];
        u64 wxx = pack2(w.x, w.x);
        u64 wyy = pack2(w.y, w.y);
        #pragma unroll
        for (int rp = 0; rp < 4; rp++) {
            u64 xp = *(const u64*)&sXT[k * 33 + rp_base + rp];
            po0[rp] = fma2(xp, wxx, po0[rp]);
            po1[rp] = fma2(xp, wyy, po1[rp]);
        }
    }

    #pragma unroll
    for (int rp = 0; rp < 4; rp++) {
        int row0 = r_base + warp * 8 + rp * 2;
        float lo0, hi0, lo1, hi1;
        unpack2(po0[rp], lo0, hi0);
        unpack2(po1[rp], lo1, hi1);
        if (row0 < nrows) {
            y[(size_t)row0 * 64 + lane]      = lo0;
            y[(size_t)row0 * 64 + lane + 32] = lo1;
        }
        if (row0 + 1 < nrows) {
            y[(size_t)(row0 + 1) * 64 + lane]      = hi0;
            y[(size_t)(row0 + 1) * 64 + lane + 32] = hi1;
        }
    }
}

// ---------------- SpMM (all rows): out = relu(L @ y + y + b) ----------------
// Block = 64 contiguous rows; edge segment staged in smem; warp = 8 rows.
__global__ __launch_bounds__(256)
void spmm_relu_kernel(const float* __restrict__ y,
                      const float* __restrict__ b,
                      float* __restrict__ out, int nrows) {
    __shared__ int2  sE[EDGE_CAP];
    __shared__ float sb[64];
    int tid = threadIdx.x;
    if (tid < 64) sb[tid] = b[tid];

    int r_base = blockIdx.x * ROWS_PER_BLOCK;
    int r_end  = min(r_base + ROWS_PER_BLOCK, nrows);
    int blk_s  = g_rowptr[r_base];
    int blk_e  = g_rowptr[r_end];
    bool fast  = (blk_e - blk_s) <= EDGE_CAP;
    int stage  = fast ? (blk_e - blk_s) : 0;
    for (int i = tid; i < stage; i += 256) sE[i] = g_edges[blk_s + i];
    __syncthreads();

    int lane = tid & 31, warp = tid >> 5;
    int r0 = r_base + warp * 8;

    #pragma unroll
    for (int rr = 0; rr < 8; rr++) {
        int row = r0 + rr;
        if (row >= nrows) break;
        const float* yr = y + (size_t)row * 64;
        float a0 = yr[lane]      + sb[lane];        // self loop + bias
        float a1 = yr[lane + 32] + sb[lane + 32];
        int s = g_rowptr[row] - blk_s, e = g_rowptr[row + 1] - blk_s;
        int i = s;
        if (fast) {
            for (; i + 8 <= e; i += 8) {
                int2 c[8];
                #pragma unroll
                for (int q = 0; q < 8; q++) c[q] = sE[i + q];
                float xs0[8], xs1[8];
                #pragma unroll
                for (int q = 0; q < 8; q++) {
                    const float* yp = y + (size_t)c[q].x * 64;
                    xs0[q] = yp[lane];  xs1[q] = yp[lane + 32];
                }
                #pragma unroll
                for (int q = 0; q < 8; q++) {
                    float v = __int_as_float(c[q].y);
                    a0 += v * xs0[q];  a1 += v * xs1[q];
                }
            }
            for (; i < e; i++) {
                int2 cc = sE[i];
                float v = __int_as_float(cc.y);
                const float* yp = y + (size_t)cc.x * 64;
                a0 += v * yp[lane];
                a1 += v * yp[lane + 32];
            }
        } else {
            for (; i < e; i++) {
                int2 cc = g_edges[blk_s + i];
                float v = __int_as_float(cc.y);
                const float* yp = y + (size_t)cc.x * 64;
                a0 += v * yp[lane];
                a1 += v * yp[lane + 32];
            }
        }
        float* op = out + (size_t)row * 64;
        op[lane]      = fmaxf(a0, 0.f);
        op[lane + 32] = fmaxf(a1, 0.f);
    }
}

// ---------------- SpMM (gathered rows, plain): z = L @ f + f ----------------
// Computes z at exactly the 32768 gathered rows (duplicates benign).
// No bias, no relu (the following indexed GEMM applies W1, b1, relu).
__global__ __launch_bounds__(256)
void spmm_idx_kernel(const int*   __restrict__ userIdx,
                     const int*   __restrict__ itemIdx,
                     const float* __restrict__ f,
                     float* __restrict__ z) {
    int tid = threadIdx.x;
    int lane = tid & 31, warp = tid >> 5;
    int base = blockIdx.x * 64 + warp * 8;     // entry index base (0..32767)

    #pragma unroll
    for (int rr = 0; rr < 8; rr++) {
        int ent = base + rr;
        int row = (ent < BATCH) ? __ldg(userIdx + ent)
                                : (__ldg(itemIdx + ent - BATCH) + NUM_USERS);
        const float* fr = f + (size_t)row * 64;
        float a0 = fr[lane];                       // self loop
        float a1 = fr[lane + 32];
        int s = g_rowptr[row], e = g_rowptr[row + 1];
        int i = s;
        for (; i + 8 <= e; i += 8) {
            int2 c[8];
            #pragma unroll
            for (int q = 0; q < 8; q++) c[q] = g_edges[i + q];
            float xs0[8], xs1[8];
            #pragma unroll
            for (int q = 0; q < 8; q++) {
                const float* fp = f + (size_t)c[q].x * 64;
                xs0[q] = fp[lane];  xs1[q] = fp[lane + 32];
            }
            #pragma unroll
            for (int q = 0; q < 8; q++) {
                float v = __int_as_float(c[q].y);
                a0 += v * xs0[q];  a1 += v * xs1[q];
            }
        }
        for (; i < e; i++) {
            int2 cc = g_edges[i];
            float v = __int_as_float(cc.y);
            const float* fp = f + (size_t)cc.x * 64;
            a0 += v * fp[lane];
            a1 += v * fp[lane + 32];
        }
        float* zp = z + (size_t)row * 64;
        zp[lane]      = a0;
        zp[lane + 32] = a1;
    }
}

// ---------------- indexed GEMM: feat2[node] = relu(z[node] @ W + b) ---------
// Block = 64 entries (nodes via userIdx/itemIdx); same f32x2 inner loop as
// gemm_kernel; bias folded into accumulator init; relu on store.
__global__ __launch_bounds__(256)
void gemm_idx_relu_kernel(const int*   __restrict__ userIdx,
                          const int*   __restrict__ itemIdx,
                          const float* __restrict__ z,
                          const float* __restrict__ W,
                          const float* __restrict__ b,
                          float* __restrict__ outF) {
    __shared__ float2 sW[64 * 32];
    __shared__ float2 sXT[64 * 33];
    __shared__ int    sNode[64];
    int tid = threadIdx.x;
    #pragma unroll
    for (int i = tid; i < 2048; i += 256) {
        int k = i >> 5, j = i & 31;
        sW[i] = make_float2(W[k * 64 + j], W[k * 64 + j + 32]);
    }
    int e_base = blockIdx.x * 64;
    if (tid < 64) {
        int ent = e_base + tid;
        sNode[tid] = (ent < BATCH) ? __ldg(userIdx + ent)
                                   : (__ldg(itemIdx + ent - BATCH) + NUM_USERS);
    }
    __syncthreads();
    #pragma unroll
    for (int i = tid; i < 4096; i += 256) {
        int row = i >> 6, k = i & 63;
        float v = z[(size_t)sNode[row] * 64 + k];
        ((float*)&sXT[k * 33 + (row >> 1)])[row & 1] = v;
    }
    __syncthreads();

    int lane = tid & 31, warp = tid >> 5;
    int rp_base = warp * 4;

    float bl = __ldg(b + lane), bh = __ldg(b + lane + 32);
    u64 po0[4], po1[4];
    #pragma unroll
    for (int rp = 0; rp < 4; rp++) {
        po0[rp] = pack2(bl, bl);
        po1[rp] = pack2(bh, bh);
    }

    #pragma unroll 4
    for (int k = 0; k < 64; k++) {
        float2 w = sW[k * 32 + lane];
        u64 wxx = pack2(w.x, w.x);
        u64 wyy = pack2(w.y, w.y);
        #pragma unroll
        for (int rp = 0; rp < 4; rp++) {
            u64 xp = *(const u64*)&sXT[k * 33 + rp_base + rp];
            po0[rp] = fma2(xp, wxx, po0[rp]);
            po1[rp] = fma2(xp, wyy, po1[rp]);
        }
    }

    #pragma unroll
    for (int rp = 0; rp < 4; rp++) {
        int er0 = warp * 8 + rp * 2;              // entry within block
        int n0 = sNode[er0], n1 = sNode[er0 + 1];
        float lo0, hi0, lo1, hi1;
        unpack2(po0[rp], lo0, hi0);
        unpack2(po1[rp], lo1, hi1);
        outF[(size_t)n0 * 64 + lane]      = fmaxf(lo0, 0.f);
        outF[(size_t)n0 * 64 + lane + 32] = fmaxf(lo1, 0.f);
        outF[(size_t)n1 * 64 + lane]      = fmaxf(hi0, 0.f);
        outF[(size_t)n1 * 64 + lane + 32] = fmaxf(hi1, 0.f);
    }
}

// ---------------- fused gather + 3-layer MLP --------------------------------
__global__ __launch_bounds__(256)
void mlp_fused_kernel(const int*   __restrict__ userIdx,
                      const int*   __restrict__ itemIdx,
                      const float* __restrict__ uEmb,
                      const float* __restrict__ iEmb,
                      const float* __restrict__ W1, const float* __restrict__ b1,
                      const float* __restrict__ W2, const float* __restrict__ b2,
                      const float* __restrict__ W3, const float* __restrict__ b3,
                      float* __restrict__ out) {
    __shared__ float2 sW[64 * 32];    // current W1 segment, paired cols
    __shared__ float  sW2[64 * 32];
    __shared__ float  sb2[32], sW3[32];
    __shared__ float  sb3;

    int tid = threadIdx.x, lane = tid & 31, warp = tid >> 5;
    #pragma unroll
    for (int i = tid; i < 2048; i += 256) sW2[i] = W2[i];
    if (tid < 32) { sb2[tid] = b2[tid]; sW3[tid] = W3[tid]; }
    if (tid == 0) sb3 = b3[0];

    int base = blockIdx.x * 64 + warp * 8;
    int unode[8], inode[8];
    #pragma unroll
    for (int r = 0; r < 8; r++) {
        unode[r] = __ldg(userIdx + base + r);
        inode[r] = __ldg(itemIdx + base + r) + NUM_USERS;
    }

    float bb0 = __ldg(b1 + lane), bb1 = __ldg(b1 + lane + 32);
    float acc0[8], acc1[8];
    #pragma unroll
    for (int r = 0; r < 8; r++) { acc0[r] = bb0; acc1[r] = bb1; }

    #pragma unroll
    for (int kk = 0; kk < 6; kk++) {
        __syncthreads();
        #pragma unroll
        for (int i = tid; i < 2048; i += 256) {
            int k = i >> 5, j = i & 31;
            sW[i] = make_float2(W1[(kk * 64 + k) * 64 + j],
                                W1[(kk * 64 + k) * 64 + j + 32]);
        }
        __syncthreads();

        int seg = (kk < 3) ? kk : kk - 3;

        float a0[8], a1[8];
        #pragma unroll
        for (int r = 0; r < 8; r++) {
            int node = (kk < 3) ? unode[r] : inode[r];
            const float* er;
            if (seg == 0)      er = node_row(uEmb, iEmb, node);
            else if (seg == 1) er = g_feat1 + (size_t)node * 64;
            else               er = g_feat2 + (size_t)node * 64;
            a0[r] = er[lane]; a1[r] = er[lane + 32];
        }
        #pragma unroll
        for (int k = 0; k < 32; k++) {
            float2 w = sW[k * 32 + lane];
            #pragma unroll
            for (int r = 0; r < 8; r++) {
                float hk = __shfl_sync(0xffffffffu, a0[r], k);
                acc0[r] += hk * w.x;  acc1[r] += hk * w.y;
            }
        }
        #pragma unroll
        for (int k = 0; k < 32; k++) {
            float2 w = sW[(k + 32) * 32 + lane];
            #pragma unroll
            for (int r = 0; r < 8; r++) {
                float hk = __shfl_sync(0xffffffffu, a1[r], k);
                acc0[r] += hk * w.x;  acc1[r] += hk * w.y;
            }
        }
    }

    // stages 2+3, in-warp
    #pragma unroll
    for (int r = 0; r < 8; r++) {
        float m0  = fmaxf(acc0[r], 0.f);
        float m1v = fmaxf(acc1[r], 0.f);
        float acc = sb2[lane];                 // lane = output col (0..31)
        #pragma unroll
        for (int k = 0; k < 32; k++) {
            float hk = __shfl_sync(0xffffffffu, m0, k);
            acc += hk * sW2[k * 32 + lane];
        }
        #pragma unroll
        for (int k = 0; k < 32; k++) {
            float hk = __shfl_sync(0xffffffffu, m1v, k);
            acc += hk * sW2[(k + 32) * 32 + lane];
        }
        float p = acc * sW3[lane];             // no ReLU after W2 (matches ref)
        #pragma unroll
        for (int off = 16; off > 0; off >>= 1)
            p += __shfl_xor_sync(0xffffffffu, p, off);
        if (lane == 0) out[base + r] = p + sb3;
    }
}

// ---------------- launch ----------------------------------------------------
extern "C" void kernel_launch(void* const* d_in, const int* in_sizes, int n_in,
                              void* d_out, int out_size) {
    const int*   userIdx = (const int*)  d_in[0];
    const int*   itemIdx = (const int*)  d_in[1];
    const int*   lapRows = (const int*)  d_in[2];
    const int*   lapCols = (const int*)  d_in[3];
    const float* lapVals = (const float*)d_in[4];
    const float* uEmb    = (const float*)d_in[5];
    const float* iEmb    = (const float*)d_in[6];
    const float* gW0     = (const float*)d_in[7];
    const float* gb0     = (const float*)d_in[8];
    const float* gW1     = (const float*)d_in[9];
    const float* gb1     = (const float*)d_in[10];
    const float* W1      = (const float*)d_in[11];
    const float* b1      = (const float*)d_in[12];
    const float* W2      = (const float*)d_in[13];
    const float* b2      = (const float*)d_in[14];
    const float* W3      = (const float*)d_in[15];
    const float* b3      = (const float*)d_in[16];
    float* out = (float*)d_out;

    const int nnz = in_sizes[2];

    float *y, *feat1, *feat2;
    cudaGetSymbolAddress((void**)&y,     g_y);
    cudaGetSymbolAddress((void**)&feat1, g_feat1);
    cudaGetSymbolAddress((void**)&feat2, g_feat2);

    const int eb = (nnz + 255) / 256;
    const int nb = (N_NODES + 63) / 64;
    const int ib = (2 * BATCH) / 64;           // 512 indexed blocks

    // CSR build (g_cnt zero on entry; scan1 restores after reading)
    hist_kernel<<<eb, 256>>>(lapRows, nnz);                       // 1
    scan1_kernel<<<NB_SCAN, 256>>>();                             // 2
    scan23_kernel<<<NB_SCAN, 256>>>(nnz);                         // 3
    scatter_kernel<<<eb, 256>>>(lapRows, lapCols, lapVals, nnz);  // 4

    // layer 1:  y = x@W0 ; feat1 = relu(L@y + y + b0)
    gemm_kernel<<<nb, 256>>>(uEmb, iEmb, gW0, y, N_NODES);        // 5
    spmm_relu_kernel<<<nb, 256>>>(y, gb0, feat1, N_NODES);        // 6

    // layer 2 (reversed order, gathered rows only):
    //   z = L@feat1 + feat1   (32768 rows)
    //   feat2 = relu(z @ W1 + b1)  (32768 rows)
    spmm_idx_kernel<<<ib, 256>>>(userIdx, itemIdx, feat1, y);     // 7
    gemm_idx_relu_kernel<<<ib, 256>>>(userIdx, itemIdx, y,
                                      gW1, gb1, feat2);           // 8

    // fused gather + 3-layer MLP
    mlp_fused_kernel<<<BATCH / 64, 256>>>(userIdx, itemIdx, uEmb, iEmb,
                                          W1, b1, W2, b2, W3, b3, out); // 9
}